// round 2
// baseline (speedup 1.0000x reference)
#include <cuda_runtime.h>
#include <math.h>

// Problem constants
#define B_      2
#define SEQ     1024
#define EMBED_  256
#define HEADS_  64
#define TOKENS  2048          // B*SEQ
#define BH      128           // B*HEADS

#define LOG2E 1.4426950408889634f

// Scratch: quantum-transformed q/k/v, layout [bh][s][4] fp32 (2 MB each)
__device__ float g_qz[BH * SEQ * 4];
__device__ float g_kz[BH * SEQ * 4];
__device__ float g_vz[BH * SEQ * 4];

// ---------------------------------------------------------------------------
// Phase A: fused QKV projection (x @ W^T for Wq,Wk,Wv) + quantum transform.
// Grid (16, 12): x = token tile (128 tokens), y = 64-column tile of the
// 768 virtual output columns (cols 0-255: Q, 256-511: K, 512-767: V).
// Block tile: 128 tokens x 64 cols, K-chunks of 32.
// Thread: tx = head-within-tile (16 heads * 4 cols), ty = token group (8 tok).
// ---------------------------------------------------------------------------
__global__ __launch_bounds__(256, 4)
void qkv_quantum_kernel(const float* __restrict__ x,
                        const float* __restrict__ Wq,
                        const float* __restrict__ Wk,
                        const float* __restrict__ Wv,
                        const float* __restrict__ params)
{
    __shared__ float xs[128 * 36];   // [token][k], stride 36 (pad)
    __shared__ float ws[32 * 68];    // [k][col], stride 68 (pad, 16B-aligned)

    const int tid = threadIdx.x;
    const int bx  = blockIdx.x;            // token tile
    const int by  = blockIdx.y;            // col tile 0..11
    const int mat = by >> 2;               // 0=Q 1=K 2=V
    const int e_base = (by & 3) * 64;      // col offset within the matrix
    const float* __restrict__ W = (mat == 0) ? Wq : (mat == 1 ? Wk : Wv);
    const int t0 = bx * 128;

    const int tx = tid & 15;               // head slot (4 consecutive cols)
    const int ty = tid >> 4;               // token group (8 tokens)

    float acc[8][4];
#pragma unroll
    for (int i = 0; i < 8; i++) {
        acc[i][0] = 0.f; acc[i][1] = 0.f; acc[i][2] = 0.f; acc[i][3] = 0.f;
    }

    for (int kb = 0; kb < 8; kb++) {
        const int k0 = kb * 32;

        // Load x tile: 128 rows x 32 floats = 1024 float4
#pragma unroll
        for (int v = 0; v < 4; v++) {
            int i  = tid + v * 256;
            int r  = i >> 3;
            int c4 = i & 7;
            float4 xv = *reinterpret_cast<const float4*>(
                x + (size_t)(t0 + r) * EMBED_ + k0 + c4 * 4);
            *reinterpret_cast<float4*>(&xs[r * 36 + c4 * 4]) = xv;
        }
        // Load W tile transposed: 64 e-rows x 32 j -> ws[j][e]
#pragma unroll
        for (int v = 0; v < 2; v++) {
            int i  = tid + v * 256;
            int e  = i >> 3;
            int j4 = i & 7;
            float4 wv = *reinterpret_cast<const float4*>(
                W + (size_t)(e_base + e) * EMBED_ + k0 + j4 * 4);
            ws[(j4 * 4 + 0) * 68 + e] = wv.x;
            ws[(j4 * 4 + 1) * 68 + e] = wv.y;
            ws[(j4 * 4 + 2) * 68 + e] = wv.z;
            ws[(j4 * 4 + 3) * 68 + e] = wv.w;
        }
        __syncthreads();

#pragma unroll 8
        for (int k = 0; k < 32; k++) {
            float4 bv = *reinterpret_cast<const float4*>(&ws[k * 68 + tx * 4]);
            float a[8];
#pragma unroll
            for (int i = 0; i < 8; i++) a[i] = xs[(ty * 8 + i) * 36 + k];
#pragma unroll
            for (int i = 0; i < 8; i++) {
                acc[i][0] = fmaf(a[i], bv.x, acc[i][0]);
                acc[i][1] = fmaf(a[i], bv.y, acc[i][1]);
                acc[i][2] = fmaf(a[i], bv.z, acc[i][2]);
                acc[i][3] = fmaf(a[i], bv.w, acc[i][3]);
            }
        }
        __syncthreads();
    }

    // Epilogue: quantum transform.
    //   z_d = cos(p_d) * cos(val_d + p_d)
    //   e0 = z1 z2 z3 ; e1 = z0 z1 ; e2 = e1 z2 ; e3 = e2 z3
    float p[4], cp[4];
#pragma unroll
    for (int d = 0; d < 4; d++) { p[d] = params[d]; cp[d] = cosf(p[d]); }

    const int h = (by & 3) * 16 + tx;      // global head 0..63
    float* __restrict__ dst = (mat == 0) ? g_qz : (mat == 1 ? g_kz : g_vz);
    const float qscale = 0.5f * LOG2E;     // scores/sqrt(dk) folded into q, log2 dom

#pragma unroll
    for (int i = 0; i < 8; i++) {
        const int t = t0 + ty * 8 + i;
        const int b = t >> 10;
        const int s = t & 1023;
        float z0 = cp[0] * cosf(acc[i][0] + p[0]);
        float z1 = cp[1] * cosf(acc[i][1] + p[1]);
        float z2 = cp[2] * cosf(acc[i][2] + p[2]);
        float z3 = cp[3] * cosf(acc[i][3] + p[3]);
        float4 o;
        o.x = z1 * z2 * z3;
        o.y = z0 * z1;
        o.z = o.y * z2;
        o.w = o.z * z3;
        if (mat == 0) { o.x *= qscale; o.y *= qscale; o.z *= qscale; o.w *= qscale; }
        *reinterpret_cast<float4*>(
            &dst[(((size_t)(b * HEADS_ + h)) * SEQ + s) * 4]) = o;
    }
}

// ---------------------------------------------------------------------------
// Phase B: attention, dk = 4.  scores in [-2,2] -> no max subtraction needed.
// Grid 512: blockIdx = bh*4 + qchunk. 256 threads, 1 query each.
// k/v for the head staged in smem (32 KB), broadcast reads in the inner loop.
// ---------------------------------------------------------------------------
__global__ __launch_bounds__(256, 4)
void attn_kernel(float* __restrict__ out)
{
    __shared__ float4 ks[SEQ];
    __shared__ float4 vs[SEQ];

    const int bh  = blockIdx.x >> 2;
    const int qc  = blockIdx.x & 3;
    const int tid = threadIdx.x;

    const float4* __restrict__ kz = reinterpret_cast<const float4*>(g_kz) + (size_t)bh * SEQ;
    const float4* __restrict__ vz = reinterpret_cast<const float4*>(g_vz) + (size_t)bh * SEQ;
#pragma unroll
    for (int v = 0; v < 4; v++) {
        int i = tid + v * 256;
        ks[i] = kz[i];
        vs[i] = vz[i];
    }
    __syncthreads();

    const int q = qc * 256 + tid;
    const float4 Q = reinterpret_cast<const float4*>(g_qz)[(size_t)bh * SEQ + q];

    float den = 0.f, a0 = 0.f, a1 = 0.f, a2 = 0.f, a3 = 0.f;
#pragma unroll 8
    for (int k = 0; k < SEQ; k++) {
        float4 K = ks[k];
        float4 V = vs[k];
        float s = fmaf(Q.x, K.x, fmaf(Q.y, K.y, fmaf(Q.z, K.z, Q.w * K.w)));
        float w;
        asm("ex2.approx.ftz.f32 %0, %1;" : "=f"(w) : "f"(s));   // q pre-scaled by 0.5*log2e
        den += w;
        a0 = fmaf(w, V.x, a0);
        a1 = fmaf(w, V.y, a1);
        a2 = fmaf(w, V.z, a2);
        a3 = fmaf(w, V.w, a3);
    }

    const float inv = __fdividef(1.f, den);
    const int b = bh >> 6;
    const int h = bh & 63;
    float4 o; o.x = a0 * inv; o.y = a1 * inv; o.z = a2 * inv; o.w = a3 * inv;
    reinterpret_cast<float4*>(out)[((size_t)(b * SEQ + q)) * (EMBED_ / 4) + h] = o;
}

// ---------------------------------------------------------------------------
extern "C" void kernel_launch(void* const* d_in, const int* in_sizes, int n_in,
                              void* d_out, int out_size)
{
    const float* x      = (const float*)d_in[0];
    const float* Wq     = (const float*)d_in[1];
    const float* Wk     = (const float*)d_in[2];
    const float* Wv     = (const float*)d_in[3];
    const float* params = (const float*)d_in[4];
    float* out = (float*)d_out;

    dim3 gA(16, 12);
    qkv_quantum_kernel<<<gA, 256>>>(x, Wq, Wk, Wv, params);
    attn_kernel<<<512, 256>>>(out);
}

// round 6
// speedup vs baseline: 1.2430x; 1.2430x over previous
#include <cuda_runtime.h>
#include <math.h>

#define B_      2
#define SEQ     1024
#define EMBED_  256
#define HEADS_  64
#define BH      128

#define LOG2E 1.4426950408889634f

typedef unsigned long long ull;

// Scratch: quantum-transformed q/k/v, layout [bh][s][4] fp32 (2 MB each)
__device__ float g_qz[BH * SEQ * 4];
__device__ float g_kz[BH * SEQ * 4];
__device__ float g_vz[BH * SEQ * 4];

// ---- packed f32x2 helpers (sm_103a FFMA2 path, PTX-only) --------------------
__device__ __forceinline__ ull pack2(float a, float b) {
    ull r; asm("mov.b64 %0, {%1,%2};" : "=l"(r) : "f"(a), "f"(b)); return r;
}
__device__ __forceinline__ void unpack2(ull v, float& a, float& b) {
    asm("mov.b64 {%0,%1}, %2;" : "=f"(a), "=f"(b) : "l"(v));
}
__device__ __forceinline__ ull fma2(ull a, ull b, ull c) {
    ull d; asm("fma.rn.f32x2 %0, %1, %2, %3;" : "=l"(d) : "l"(a), "l"(b), "l"(c)); return d;
}
__device__ __forceinline__ ull mul2(ull a, ull b) {
    ull d; asm("mul.rn.f32x2 %0, %1, %2;" : "=l"(d) : "l"(a), "l"(b)); return d;
}
__device__ __forceinline__ ull add2(ull a, ull b) {
    ull d; asm("add.rn.f32x2 %0, %1, %2;" : "=l"(d) : "l"(a), "l"(b)); return d;
}
__device__ __forceinline__ float ex2f(float x) {
    float r; asm("ex2.approx.ftz.f32 %0, %1;" : "=f"(r) : "f"(x)); return r;
}

// ---------------------------------------------------------------------------
// Phase A: fused QKV projection + quantum transform, packed-f32x2 inner loop.
// Grid (16, 12): x = 128-token tile, y = 64-col tile of 768 virtual cols.
// ---------------------------------------------------------------------------
__global__ __launch_bounds__(256, 4)
void qkv_quantum_kernel(const float* __restrict__ x,
                        const float* __restrict__ Wq,
                        const float* __restrict__ Wk,
                        const float* __restrict__ Wv,
                        const float* __restrict__ params)
{
    __shared__ __align__(16) float xs[128 * 36];   // [token][k]
    __shared__ __align__(16) float ws[32 * 68];    // [k][col]

    const int tid = threadIdx.x;
    const int bx  = blockIdx.x;
    const int by  = blockIdx.y;
    const int mat = by >> 2;               // 0=Q 1=K 2=V
    const int e_base = (by & 3) * 64;
    const float* __restrict__ W = (mat == 0) ? Wq : (mat == 1 ? Wk : Wv);
    const int t0 = bx * 128;

    const int tx = tid & 15;               // head slot (4 cols)
    const int ty = tid >> 4;               // token group (8 tokens)

    ull acc2[8][2];                        // [row][(c0,c1),(c2,c3)]
#pragma unroll
    for (int i = 0; i < 8; i++) { acc2[i][0] = 0ull; acc2[i][1] = 0ull; }

    for (int kb = 0; kb < 8; kb++) {
        const int k0 = kb * 32;

#pragma unroll
        for (int v = 0; v < 4; v++) {
            int i  = tid + v * 256;
            int r  = i >> 3;
            int c4 = i & 7;
            float4 xv = *reinterpret_cast<const float4*>(
                x + (size_t)(t0 + r) * EMBED_ + k0 + c4 * 4);
            *reinterpret_cast<float4*>(&xs[r * 36 + c4 * 4]) = xv;
        }
#pragma unroll
        for (int v = 0; v < 2; v++) {
            int i  = tid + v * 256;
            int e  = i >> 3;
            int j4 = i & 7;
            float4 wv = *reinterpret_cast<const float4*>(
                W + (size_t)(e_base + e) * EMBED_ + k0 + j4 * 4);
            ws[(j4 * 4 + 0) * 68 + e] = wv.x;
            ws[(j4 * 4 + 1) * 68 + e] = wv.y;
            ws[(j4 * 4 + 2) * 68 + e] = wv.z;
            ws[(j4 * 4 + 3) * 68 + e] = wv.w;
        }
        __syncthreads();

#pragma unroll 4
        for (int k = 0; k < 32; k++) {
            ulonglong2 bv = *reinterpret_cast<const ulonglong2*>(&ws[k * 68 + tx * 4]);
#pragma unroll
            for (int i = 0; i < 8; i++) {
                float a = xs[(ty * 8 + i) * 36 + k];
                ull a2 = pack2(a, a);
                acc2[i][0] = fma2(a2, bv.x, acc2[i][0]);
                acc2[i][1] = fma2(a2, bv.y, acc2[i][1]);
            }
        }
        __syncthreads();
    }

    // Epilogue: z_d = cos(p_d)*cos(val_d + p_d);
    //   e0=z1 z2 z3; e1=z0 z1; e2=e1 z2; e3=e2 z3
    float p[4], cp[4];
#pragma unroll
    for (int d = 0; d < 4; d++) { p[d] = params[d]; cp[d] = __cosf(p[d]); }

    const int h = (by & 3) * 16 + tx;
    float* __restrict__ dst = (mat == 0) ? g_qz : (mat == 1 ? g_kz : g_vz);
    const float qscale = 0.5f * LOG2E;     // 1/sqrt(dk)=0.5 folded with log2e into q

#pragma unroll
    for (int i = 0; i < 8; i++) {
        const int t = t0 + ty * 8 + i;
        const int b = t >> 10;
        const int s = t & 1023;
        float v0, v1, v2, v3;
        unpack2(acc2[i][0], v0, v1);
        unpack2(acc2[i][1], v2, v3);
        float z0 = cp[0] * __cosf(v0 + p[0]);
        float z1 = cp[1] * __cosf(v1 + p[1]);
        float z2 = cp[2] * __cosf(v2 + p[2]);
        float z3 = cp[3] * __cosf(v3 + p[3]);
        float4 o;
        o.x = z1 * z2 * z3;
        o.y = z0 * z1;
        o.z = o.y * z2;
        o.w = o.z * z3;
        if (mat == 0) { o.x *= qscale; o.y *= qscale; o.z *= qscale; o.w *= qscale; }
        *reinterpret_cast<float4*>(
            &dst[(((size_t)(b * HEADS_ + h)) * SEQ + s) * 4]) = o;
    }
}

// ---------------------------------------------------------------------------
// Phase B: attention, dk=4, fully packed over k-pairs.
// smem: per k-pair, 4 float4 = {(KX,KY),(KZ,KW),(VX,VY),(VZ,VW)} where
// KX=(kx[2i],kx[2i+1]) etc. Grid 256 = bh*2; 256 threads; 2 queries/thread.
// Scores bounded in [-2,2] -> no softmax max needed; q pre-scaled by 0.5*log2e.
// ---------------------------------------------------------------------------
__global__ __launch_bounds__(256)
void attn_kernel(float* __restrict__ out)
{
    __shared__ __align__(16) float4 kv[512][4];

    const int bh  = blockIdx.x >> 1;
    const int qh  = blockIdx.x & 1;
    const int tid = threadIdx.x;

    const float4* __restrict__ kz4 = reinterpret_cast<const float4*>(g_kz) + (size_t)bh * SEQ;
    const float4* __restrict__ vz4 = reinterpret_cast<const float4*>(g_vz) + (size_t)bh * SEQ;

#pragma unroll
    for (int v = 0; v < 2; v++) {
        int i = tid + v * 256;
        float4 K0 = kz4[2 * i], K1 = kz4[2 * i + 1];
        kv[i][0] = make_float4(K0.x, K1.x, K0.y, K1.y);
        kv[i][1] = make_float4(K0.z, K1.z, K0.w, K1.w);
        float4 V0 = vz4[2 * i], V1 = vz4[2 * i + 1];
        kv[i][2] = make_float4(V0.x, V1.x, V0.y, V1.y);
        kv[i][3] = make_float4(V0.z, V1.z, V0.w, V1.w);
    }
    __syncthreads();

    const int q0 = qh * 512 + tid;         // second query at q0 + 256
    ull Q[2][4];
#pragma unroll
    for (int j = 0; j < 2; j++) {
        float4 Qv = reinterpret_cast<const float4*>(g_qz)[(size_t)bh * SEQ + q0 + j * 256];
        Q[j][0] = pack2(Qv.x, Qv.x);
        Q[j][1] = pack2(Qv.y, Qv.y);
        Q[j][2] = pack2(Qv.z, Qv.z);
        Q[j][3] = pack2(Qv.w, Qv.w);
    }

    ull aX[2] = {0ull, 0ull}, aY[2] = {0ull, 0ull};
    ull aZ[2] = {0ull, 0ull}, aW[2] = {0ull, 0ull};
    ull dn[2] = {0ull, 0ull};

#pragma unroll 4
    for (int kp = 0; kp < 512; kp++) {
        const ulonglong2* u = reinterpret_cast<const ulonglong2*>(kv + kp);
        ulonglong2 kxy = u[0];
        ulonglong2 kzw = u[1];
        ulonglong2 vxy = u[2];
        ulonglong2 vzw = u[3];
#pragma unroll
        for (int j = 0; j < 2; j++) {
            ull s2 = mul2(Q[j][0], kxy.x);
            s2 = fma2(Q[j][1], kxy.y, s2);
            s2 = fma2(Q[j][2], kzw.x, s2);
            s2 = fma2(Q[j][3], kzw.y, s2);
            float s0, s1; unpack2(s2, s0, s1);
            ull w2 = pack2(ex2f(s0), ex2f(s1));
            dn[j] = add2(dn[j], w2);
            aX[j] = fma2(w2, vxy.x, aX[j]);
            aY[j] = fma2(w2, vxy.y, aY[j]);
            aZ[j] = fma2(w2, vzw.x, aZ[j]);
            aW[j] = fma2(w2, vzw.y, aW[j]);
        }
    }

    const int b = bh >> 6;
    const int h = bh & 63;
#pragma unroll
    for (int j = 0; j < 2; j++) {
        const int q = q0 + j * 256;
        float d0, d1, x0, x1, y0, y1, z0, z1, w0, w1;
        unpack2(dn[j], d0, d1);
        unpack2(aX[j], x0, x1);
        unpack2(aY[j], y0, y1);
        unpack2(aZ[j], z0, z1);
        unpack2(aW[j], w0, w1);
        const float inv = __fdividef(1.f, d0 + d1);
        float4 o;
        o.x = (x0 + x1) * inv;
        o.y = (y0 + y1) * inv;
        o.z = (z0 + z1) * inv;
        o.w = (w0 + w1) * inv;
        reinterpret_cast<float4*>(out)[((size_t)(b * SEQ + q)) * (EMBED_ / 4) + h] = o;
    }
}

// ---------------------------------------------------------------------------
extern "C" void kernel_launch(void* const* d_in, const int* in_sizes, int n_in,
                              void* d_out, int out_size)
{
    const float* x      = (const float*)d_in[0];
    const float* Wq     = (const float*)d_in[1];
    const float* Wk     = (const float*)d_in[2];
    const float* Wv     = (const float*)d_in[3];
    const float* params = (const float*)d_in[4];
    float* out = (float*)d_out;

    dim3 gA(16, 12);
    qkv_quantum_kernel<<<gA, 256>>>(x, Wq, Wk, Wv, params);
    attn_kernel<<<256, 256>>>(out);
}